// round 12
// baseline (speedup 1.0000x reference)
#include <cuda_runtime.h>
#include <cuda_fp16.h>
#include <math.h>
#include <stdint.h>

#define BB 2
#define SQ 1024
#define DD 768
#define NH 12
#define DK 64
#define FF 3072
#define NL 12
#define NV 50257
#define NVP 50432
#define NT (BB*SQ)

// ---------------- scratch (allocation-free: __device__ globals) ----------------
__device__ float  g_x   [NT*DD];
__device__ __half g_xr  [NT*DD];
__device__ __half g_qkv [3*NT*DD];
__device__ __half g_ctx [NT*DD];
__device__ float  g_tmp [NT*DD];
__device__ float  g_tmp2[NT*DD];
__device__ __half g_h   [NT*FF];
__device__ __half g_vti [(size_t)BB*NH*SQ*DK];
// pair-interleaved ([k/16][n][16 halves]) fp16 weights
__device__ __half g_wqi[NL*DD*DD];
__device__ __half g_wki[NL*DD*DD];
__device__ __half g_wvi[NL*DD*DD];
__device__ __half g_woi[NL*DD*DD];
__device__ __half g_w1i[(size_t)NL*DD*FF];
__device__ __half g_w2i[(size_t)NL*FF*DD];
__device__ __half g_wpi[(size_t)DD*NVP];

// ---------------- helpers ----------------
__device__ __forceinline__ void mma_f16(float* c, const unsigned* a, const unsigned* b) {
    asm volatile(
        "mma.sync.aligned.m16n8k16.row.col.f32.f16.f16.f32 "
        "{%0,%1,%2,%3}, {%4,%5,%6,%7}, {%8,%9}, {%0,%1,%2,%3};"
        : "+f"(c[0]), "+f"(c[1]), "+f"(c[2]), "+f"(c[3])
        : "r"(a[0]), "r"(a[1]), "r"(a[2]), "r"(a[3]), "r"(b[0]), "r"(b[1]));
}

__device__ __forceinline__ float gelu_f(float v) {
    return 0.5f * v * (1.f + erff(v * 0.70710678118654752f));
}

__device__ __forceinline__ uint32_t smem_u32(const void* p) {
    uint32_t a;
    asm("{ .reg .u64 t; cvta.to.shared.u64 t, %1; cvt.u32.u64 %0, t; }" : "=r"(a) : "l"(p));
    return a;
}
__device__ __forceinline__ void cpa16(uint32_t saddr, const void* g) {
    asm volatile("cp.async.cg.shared.global [%0], [%1], 16;" :: "r"(saddr), "l"(g));
}

// ---------------- embedding (fp32 x + fp16 xr) ----------------
__global__ void k_embed(const int* __restrict__ ids, const float* __restrict__ emb,
                        const float* __restrict__ pe, float* __restrict__ x,
                        __half* __restrict__ xr)
{
    int i = blockIdx.x * 256 + threadIdx.x;
    if (i >= NT * DD) return;
    int t = i / DD;
    int d = i - t * DD;
    int s = t % SQ;
    float v = emb[(size_t)ids[t] * DD + d] + pe[(size_t)s * DD + d];
    x[i] = v;
    xr[i] = __float2half_rn(v);
}

// ---------------- interleave + fp16 weights: out[k/16][n][16h] pair order ----------------
__global__ void k_ilv(const float* __restrict__ in, __half* __restrict__ out,
                      int Kd, int Nd, int Nout)
{
    __shared__ float sm[64][33];
    int z = blockIdx.z;
    in  += (size_t)z * Kd * Nd;
    out += (size_t)z * Kd * Nout;
    int kblk = blockIdx.x * 64;
    int n0 = blockIdx.y * 32;
    int tid = threadIdx.x;
    int tx = tid & 31, ty = tid >> 5;

    #pragma unroll
    for (int it = 0; it < 8; it++) {
        int kl = ty + it * 8;
        int n = n0 + tx;
        sm[kl][tx] = (n < Nd) ? in[(size_t)(kblk + kl) * Nd + n] : 0.f;
    }
    __syncthreads();
    #pragma unroll
    for (int it = 0; it < 4; it++) {
        int idx = tid + it * 256;
        int kb_l = idx >> 8;
        int rem = idx & 255;
        int n_l = rem >> 3;
        int pos = rem & 7;
        int i = (pos & 1) ? (pos >> 1) + 4 : (pos >> 1);
        int k_l = kb_l * 16 + 2 * i;
        __half2 hv = __floats2half2_rn(sm[k_l][n_l], sm[k_l + 1][n_l]);
        *(__half2*)&out[(((size_t)(kblk >> 4) + kb_l) * Nout + n0 + n_l) * 16 + pos * 2] = hv;
    }
}

// ---------------- per-head V interleave: vt[bh][kb][d][16h] pair order ----------------
__global__ void k_vilv(const __half* __restrict__ v, __half* __restrict__ vt)
{
    __shared__ uint32_t sm[64][33];
    int bh = blockIdx.y;
    int b = bh / NH, h = bh - b * NH;
    int s0 = blockIdx.x * 64;
    int tid = threadIdx.x;
    int sl = tid >> 2, d0 = (tid & 3) * 16;
    const __half* vp = v + (size_t)(b * SQ + s0 + sl) * DD + h * DK + d0;
    uint4 a = *(const uint4*)vp;
    uint4 c = *(const uint4*)(vp + 8);
    uint32_t* row = &sm[sl][d0 >> 1];
    row[0] = a.x; row[1] = a.y; row[2] = a.z; row[3] = a.w;
    row[4] = c.x; row[5] = c.y; row[6] = c.z; row[7] = c.w;
    __syncthreads();
    uint32_t* outp = (uint32_t*)(vt + (size_t)bh * SQ * DK);
    #pragma unroll
    for (int it = 0; it < 4; it++) {
        int idx = it * 256 + tid;
        int kb = idx >> 8, rem = idx & 255;
        int dp = rem >> 3, pi = rem & 7;
        int pos = 2 * (pi & 3) + (pi >> 2);
        int sl0 = kb * 16 + 2 * pi;
        uint32_t lo = sm[sl0][dp], hi = sm[sl0 + 1][dp];
        uint32_t r0 = __byte_perm(lo, hi, 0x5410);
        uint32_t r1 = __byte_perm(lo, hi, 0x7632);
        int kbg = (s0 >> 4) + kb;
        outp[((size_t)kbg * 64 + 2 * dp) * 8 + pos]     = r0;
        outp[((size_t)kbg * 64 + 2 * dp + 1) * 8 + pos] = r1;
    }
}

// =====================================================================
// fp16 MMA GEMM core: 128 threads, 4 warps (2m x 2n), warp tile 64x64.
// CTA 128x128, BK=64, double-buffered. A reg-prefetch -> pair-interleave
// (stride 40 u32); B pre-interleaved gmem -> cp.async.
// =====================================================================
#define GM_SMEM ((size_t)18432 * 4)

__device__ __forceinline__ void gmma_core(
    const __half* __restrict__ A, const __half* __restrict__ B,
    const float* __restrict__ bias, float* __restrict__ C, __half* __restrict__ Ch,
    int N, int ldb, int lda, int Klen, int koff, int act,
    int m0, int n0, uint32_t* sm)
{
    uint32_t* As0 = sm;
    uint32_t* Bs0 = sm + 5120;
    uint32_t* As1 = sm + 9216;
    uint32_t* Bs1 = sm + 14336;

    int tid = threadIdx.x;
    int lane = tid & 31, wid = tid >> 5;
    int wm = (wid >> 1) << 6;       // 0 / 64
    int wn = (wid & 1) << 6;        // 0 / 64
    int g = lane >> 2, tig = lane & 3;

    int aRow = tid;                  // 0..127
    int bkb = tid >> 5;              // 0..3
    int bn0 = tid & 31;              // n base; covers bn0, +32, +64, +96

    const __half* Ap = A + (size_t)(m0 + aRow) * lda + koff;
    const __half* Bp = B + ((size_t)((koff >> 4) + bkb) * ldb + n0 + bn0) * 16;
    uint32_t b0a = smem_u32(Bs0 + bkb * 1024 + bn0 * 8);
    uint32_t b1a = smem_u32(Bs1 + bkb * 1024 + bn0 * 8);

    const int S = Klen >> 6;
    const size_t bstep = (size_t)4 * ldb * 16;   // halves per stage

    // prologue: B stage0 (4 n-entries x 2 cpa16), A stage0 regs
    #pragma unroll
    for (int j = 0; j < 4; j++) {
        cpa16(b0a + j * 1024, Bp + j * 512);
        cpa16(b0a + j * 1024 + 16, Bp + j * 512 + 8);
    }
    asm volatile("cp.async.commit_group;" ::: "memory");
    uint4 ra[8];
    #pragma unroll
    for (int i = 0; i < 8; i++) ra[i] = *(const uint4*)(Ap + 8 * i);

    float acc[4][8][4] = {};

    for (int s = 0; s < S; s++) {
        int buf = s & 1;
        uint32_t* As = buf ? As1 : As0;
        uint32_t* Bs = buf ? Bs1 : Bs0;

        // store A pairs interleaved, 4 blocks of 16 k
        {
            uint32_t* dst = As + aRow * 40;
            #pragma unroll
            for (int kb = 0; kb < 4; kb++) {
                uint4 lo = ra[2 * kb], hi = ra[2 * kb + 1];
                *(uint4*)(dst + kb * 8)     = make_uint4(lo.x, hi.x, lo.y, hi.y);
                *(uint4*)(dst + kb * 8 + 4) = make_uint4(lo.z, hi.z, lo.w, hi.w);
            }
        }

        if (s + 1 < S) {
            const __half* Ap2 = Ap + (s + 1) * 64;
            #pragma unroll
            for (int i = 0; i < 8; i++) ra[i] = *(const uint4*)(Ap2 + 8 * i);
            const __half* Bp2 = Bp + (size_t)(s + 1) * bstep;
            uint32_t ba = buf ? b0a : b1a;
            #pragma unroll
            for (int j = 0; j < 4; j++) {
                cpa16(ba + j * 1024, Bp2 + j * 512);
                cpa16(ba + j * 1024 + 16, Bp2 + j * 512 + 8);
            }
            asm volatile("cp.async.commit_group;" ::: "memory");
            asm volatile("cp.async.wait_group 1;" ::: "memory");
        } else {
            asm volatile("cp.async.wait_group 0;" ::: "memory");
        }
        __syncthreads();

        #pragma unroll
        for (int kb = 0; kb < 4; kb++) {
            unsigned af[4][4], bf[8][2];
            #pragma unroll
            for (int mt = 0; mt < 4; mt++) {
                int r = wm + mt * 16 + g;
                uint2 pa = *(const uint2*)(As + r * 40 + kb * 8 + 2 * tig);
                uint2 pb = *(const uint2*)(As + (r + 8) * 40 + kb * 8 + 2 * tig);
                af[mt][0] = pa.x; af[mt][2] = pa.y;
                af[mt][1] = pb.x; af[mt][3] = pb.y;
            }
            #pragma unroll
            for (int nt = 0; nt < 8; nt++) {
                int c = wn + nt * 8 + g;
                uint2 pk = *(const uint2*)(Bs + kb * 1024 + c * 8 + 2 * tig);
                bf[nt][0] = pk.x; bf[nt][1] = pk.y;
            }
            #pragma unroll
            for (int mt = 0; mt < 4; mt++)
                #pragma unroll
                for (int nt = 0; nt < 8; nt++)
                    mma_f16(acc[mt][nt], af[mt], bf[nt]);
        }
        __syncthreads();
    }

    const bool fastC = (n0 + 128 <= N) && ((N & 3) == 0);
    #pragma unroll
    for (int mt = 0; mt < 4; mt++) {
        #pragma unroll
        for (int nt = 0; nt < 8; nt++) {
            int row = m0 + wm + mt * 16 + g;
            int col = n0 + wn + nt * 8 + 2 * tig;
            float c0 = acc[mt][nt][0], c1 = acc[mt][nt][1];
            float c2 = acc[mt][nt][2], c3 = acc[mt][nt][3];
            if (Ch) {
                float b0 = bias ? bias[col] : 0.f;
                float b1 = bias ? bias[col + 1] : 0.f;
                c0 += b0; c1 += b1; c2 += b0; c3 += b1;
                if (act) { c0 = gelu_f(c0); c1 = gelu_f(c1); c2 = gelu_f(c2); c3 = gelu_f(c3); }
                *(__half2*)&Ch[(size_t)row * N + col]       = __floats2half2_rn(c0, c1);
                *(__half2*)&Ch[(size_t)(row + 8) * N + col] = __floats2half2_rn(c2, c3);
            } else if (fastC) {
                float b0 = bias ? bias[col] : 0.f;
                float b1 = bias ? bias[col + 1] : 0.f;
                c0 += b0; c1 += b1; c2 += b0; c3 += b1;
                if (act) { c0 = gelu_f(c0); c1 = gelu_f(c1); c2 = gelu_f(c2); c3 = gelu_f(c3); }
                *(float2*)&C[(size_t)row * N + col]       = make_float2(c0, c1);
                *(float2*)&C[(size_t)(row + 8) * N + col] = make_float2(c2, c3);
            } else {
                if (col < N) {
                    float b0 = bias ? bias[col] : 0.f;
                    float u0 = c0 + b0, u2 = c2 + b0;
                    if (act) { u0 = gelu_f(u0); u2 = gelu_f(u2); }
                    C[(size_t)row * N + col] = u0;
                    C[(size_t)(row + 8) * N + col] = u2;
                }
                if (col + 1 < N) {
                    float b1 = bias ? bias[col + 1] : 0.f;
                    float u1 = c1 + b1, u3 = c3 + b1;
                    if (act) { u1 = gelu_f(u1); u3 = gelu_f(u3); }
                    C[(size_t)row * N + col + 1] = u1;
                    C[(size_t)(row + 8) * N + col + 1] = u3;
                }
            }
        }
    }
}

__global__ void __launch_bounds__(128, 2)
k_gmma(const __half* __restrict__ A, const __half* __restrict__ B,
       const float* __restrict__ bias, float* __restrict__ C, __half* __restrict__ Ch,
       int N, int ldb, int K, int act)
{
    extern __shared__ uint32_t smu[];
    gmma_core(A, B, bias, C, Ch, N, ldb, K, K, 0, act,
              blockIdx.y * 128, blockIdx.x * 128, smu);
}

__global__ void __launch_bounds__(128, 2)
k_gmma_m(const __half* __restrict__ A, const __half* __restrict__ B,
         const float* __restrict__ bias, float* __restrict__ C,
         int N, int ldb, int K)
{
    extern __shared__ uint32_t smu[];
    gmma_core(A, B, bias, C, nullptr, N, ldb, K, K, 0, 0,
              blockIdx.x * 128, blockIdx.y * 128, smu);
}

__global__ void __launch_bounds__(128, 2)
k_gmma_sk(const __half* __restrict__ A, const __half* __restrict__ B,
          const float* __restrict__ bias, float* __restrict__ CA,
          float* __restrict__ CB, int N, int ldb, int lda, int Khalf)
{
    extern __shared__ uint32_t smu[];
    int z = blockIdx.z;
    float* C = z ? CB : CA;
    const float* bz = z ? nullptr : bias;
    gmma_core(A, B, bz, C, nullptr, N, ldb, lda, Khalf, z * Khalf, 0,
              blockIdx.y * 128, blockIdx.x * 128, smu);
}

__global__ void __launch_bounds__(128, 2)
k_qkv(const __half* __restrict__ X, const __half* __restrict__ Wq,
      const __half* __restrict__ Wk, const __half* __restrict__ Wv,
      __half* __restrict__ QKV)
{
    extern __shared__ uint32_t smu[];
    int z = blockIdx.z;
    const __half* W = (z == 0) ? Wq : (z == 1) ? Wk : Wv;
    __half* O = QKV + (size_t)z * NT * DD;
    gmma_core(X, W, nullptr, nullptr, O, DD, DD, DD, DD, 0, 0,
              blockIdx.y * 128, blockIdx.x * 128, smu);
}

// =====================================================================
// Flash attention, fp16 m16n8k16 (unchanged from R11)
// =====================================================================
#define FA_SMEM (14912 * 4)

__global__ void __launch_bounds__(256, 2)
k_fattn(const __half* __restrict__ Q, const __half* __restrict__ K,
        const __half* __restrict__ Vt, const int* __restrict__ mask,
        __half* __restrict__ ctx)
{
    extern __shared__ uint32_t smu[];
    uint32_t* Qs = smu;
    uint32_t* Ks = smu + 5120;
    uint32_t* Vs = smu + 7680;
    uint32_t* Ps = smu + 9728;
    float* msk = (float*)(smu + 14848);

    int bh = blockIdx.y;
    int b = bh / NH, h = bh - b * NH;
    int i0 = blockIdx.x * 128;

    const __half* qb = Q + (size_t)b * SQ * DD + h * DK;
    const __half* kbp = K + (size_t)b * SQ * DD + h * DK;
    const __half* vth = Vt + (size_t)bh * SQ * DK;
    __half* cb = ctx + (size_t)b * SQ * DD + h * DK;
    const int* mrow = mask + (size_t)b * SQ;

    int tid = threadIdx.x;
    int lane = tid & 31, w = tid >> 5;
    int g = lane >> 2, tig = lane & 3;
    int wr = w * 16;

    {
        int r = tid >> 1, sel = tid & 1;
        const __half* qp = qb + (size_t)(i0 + r) * DD + sel * 32;
        uint4 a0 = *(const uint4*)qp;
        uint4 a1 = *(const uint4*)(qp + 8);
        uint4 a2 = *(const uint4*)(qp + 16);
        uint4 a3 = *(const uint4*)(qp + 24);
        uint32_t* dst = Qs + r * 40 + sel * 16;
        *(uint4*)(dst)      = make_uint4(a0.x, a1.x, a0.y, a1.y);
        *(uint4*)(dst + 4)  = make_uint4(a0.z, a1.z, a0.w, a1.w);
        *(uint4*)(dst + 8)  = make_uint4(a2.x, a3.x, a2.y, a3.y);
        *(uint4*)(dst + 12) = make_uint4(a2.z, a3.z, a2.w, a3.w);
    }

    float oacc[8][4] = {};
    float mr0 = -1e30f, mr1 = -1e30f, l0 = 0.f, l1 = 0.f;

    for (int kt = 0; kt < SQ; kt += 64) {
        __syncthreads();
        {
            uint32_t dsta = smem_u32(Vs) + tid * 32;
            const __half* src = vth + (size_t)(kt >> 4) * 1024 + tid * 16;
            cpa16(dsta, src);
            cpa16(dsta + 16, src + 8);
            asm volatile("cp.async.commit_group;" ::: "memory");
        }
        {
            int r = tid >> 2, qk = tid & 3;
            const __half* kp = kbp + (size_t)(kt + r) * DD + qk * 16;
            uint4 a0 = *(const uint4*)kp;
            uint4 a1 = *(const uint4*)(kp + 8);
            uint32_t* dst = Ks + r * 40 + qk * 8;
            *(uint4*)(dst)     = make_uint4(a0.x, a1.x, a0.y, a1.y);
            *(uint4*)(dst + 4) = make_uint4(a0.z, a1.z, a0.w, a1.w);
        }
        if (tid < 64) msk[tid] = (mrow[kt + tid] == 0) ? -1e9f : 0.f;
        asm volatile("cp.async.wait_group 0;" ::: "memory");
        __syncthreads();

        float sacc[8][4] = {};
        #pragma unroll
        for (int m = 0; m < 4; m++) {
            unsigned af[4];
            {
                uint2 pa = *(const uint2*)(Qs + (wr + g) * 40 + m * 8 + 2 * tig);
                uint2 pb = *(const uint2*)(Qs + (wr + g + 8) * 40 + m * 8 + 2 * tig);
                af[0] = pa.x; af[2] = pa.y;
                af[1] = pb.x; af[3] = pb.y;
            }
            #pragma unroll
            for (int j = 0; j < 8; j++) {
                uint2 pk = *(const uint2*)(Ks + (j * 8 + g) * 40 + m * 8 + 2 * tig);
                unsigned bf[2] = { pk.x, pk.y };
                mma_f16(sacc[j], af, bf);
            }
        }

        float tm0 = -1e30f, tm1 = -1e30f;
        #pragma unroll
        for (int j = 0; j < 8; j++) {
            int c = j * 8 + 2 * tig;
            float a0 = msk[c], a1 = msk[c + 1];
            sacc[j][0] = sacc[j][0] * 0.125f + a0;
            sacc[j][1] = sacc[j][1] * 0.125f + a1;
            sacc[j][2] = sacc[j][2] * 0.125f + a0;
            sacc[j][3] = sacc[j][3] * 0.125f + a1;
            tm0 = fmaxf(tm0, fmaxf(sacc[j][0], sacc[j][1]));
            tm1 = fmaxf(tm1, fmaxf(sacc[j][2], sacc[j][3]));
        }
        tm0 = fmaxf(tm0, __shfl_xor_sync(0xffffffffu, tm0, 1));
        tm0 = fmaxf(tm0, __shfl_xor_sync(0xffffffffu, tm0, 2));
        tm1 = fmaxf(tm1, __shfl_xor_sync(0xffffffffu, tm1, 1));
        tm1 = fmaxf(tm1, __shfl_xor_sync(0xffffffffu, tm1, 2));

        float mn0 = fmaxf(mr0, tm0), mn1 = fmaxf(mr1, tm1);
        float al0 = __expf(mr0 - mn0), al1 = __expf(mr1 - mn1);

        __syncwarp();
        float ts0 = 0.f, ts1 = 0.f;
        #pragma unroll
        for (int j = 0; j < 8; j++) {
            float p0v = __expf(sacc[j][0] - mn0);
            float p1v = __expf(sacc[j][1] - mn0);
            float p2v = __expf(sacc[j][2] - mn1);
            float p3v = __expf(sacc[j][3] - mn1);
            ts0 += p0v + p1v;
            ts1 += p2v + p3v;
            int m = j >> 1;
            int pi = (j & 1) * 4 + tig;
            int pos = 2 * (pi & 3) + (pi >> 2);
            *(__half2*)(Ps + (wr + g) * 40 + m * 8 + pos)     = __floats2half2_rn(p0v, p1v);
            *(__half2*)(Ps + (wr + g + 8) * 40 + m * 8 + pos) = __floats2half2_rn(p2v, p3v);
        }
        ts0 += __shfl_xor_sync(0xffffffffu, ts0, 1);
        ts0 += __shfl_xor_sync(0xffffffffu, ts0, 2);
        ts1 += __shfl_xor_sync(0xffffffffu, ts1, 1);
        ts1 += __shfl_xor_sync(0xffffffffu, ts1, 2);
        l0 = l0 * al0 + ts0;
        l1 = l1 * al1 + ts1;
        mr0 = mn0; mr1 = mn1;

        #pragma unroll
        for (int j = 0; j < 8; j++) {
            oacc[j][0] *= al0; oacc[j][1] *= al0;
            oacc[j][2] *= al1; oacc[j][3] *= al1;
        }
        __syncwarp();

        #pragma unroll
        for (int m = 0; m < 4; m++) {
            unsigned af[4];
            {
                uint2 pa = *(const uint2*)(Ps + (wr + g) * 40 + m * 8 + 2 * tig);
                uint2 pb = *(const uint2*)(Ps + (wr + g + 8) * 40 + m * 8 + 2 * tig);
                af[0] = pa.x; af[2] = pa.y;
                af[1] = pb.x; af[3] = pb.y;
            }
            #pragma unroll
            for (int j = 0; j < 8; j++) {
                uint2 pk = *(const uint2*)(Vs + m * 512 + (j * 8 + g) * 8 + 2 * tig);
                unsigned bf[2] = { pk.x, pk.y };
                mma_f16(oacc[j], af, bf);
            }
        }
    }

    float il0 = 1.f / l0, il1 = 1.f / l1;
    int r0 = i0 + wr + g;
    #pragma unroll
    for (int j = 0; j < 8; j++) {
        int c = j * 8 + 2 * tig;
        *(__half2*)&cb[(size_t)r0 * DD + c] =
            __floats2half2_rn(oacc[j][0] * il0, oacc[j][1] * il0);
        *(__half2*)&cb[(size_t)(r0 + 8) * DD + c] =
            __floats2half2_rn(oacc[j][2] * il1, oacc[j][3] * il1);
    }
}

// ---------------- LayerNorm(x (+ ra) (+ rb)); outputs fp32 + fp16 ----------------
__global__ void k_addln3(const float* __restrict__ X, const float* __restrict__ RA,
                         const float* __restrict__ RB,
                         const float* __restrict__ g, const float* __restrict__ bb,
                         float* __restrict__ O, __half* __restrict__ Or)
{
    int r = blockIdx.x;
    const float* xrow = X + (size_t)r * DD;
    const float* ra = RA ? (RA + (size_t)r * DD) : nullptr;
    const float* rbp = RB ? (RB + (size_t)r * DD) : nullptr;
    float* orow = O + (size_t)r * DD;
    __half* orow2 = Or + (size_t)r * DD;

    int tid = threadIdx.x;
    __shared__ float rbuf[8];

    float v[3];
    float s = 0.f;
    #pragma unroll
    for (int j = 0; j < 3; j++) {
        int c = tid * 3 + j;
        float x = xrow[c];
        if (ra) x += ra[c];
        if (rbp) x += rbp[c];
        v[j] = x;
        s += x;
    }
    #pragma unroll
    for (int o = 16; o; o >>= 1) s += __shfl_xor_sync(0xffffffffu, s, o);
    __syncthreads();
    if ((tid & 31) == 0) rbuf[tid >> 5] = s;
    __syncthreads();
    s = rbuf[0];
    #pragma unroll
    for (int w = 1; w < 8; w++) s += rbuf[w];
    float mean = s * (1.f / DD);

    float s2 = 0.f;
    #pragma unroll
    for (int j = 0; j < 3; j++) { float d = v[j] - mean; s2 += d * d; }
    #pragma unroll
    for (int o = 16; o; o >>= 1) s2 += __shfl_xor_sync(0xffffffffu, s2, o);
    __syncthreads();
    if ((tid & 31) == 0) rbuf[tid >> 5] = s2;
    __syncthreads();
    s2 = rbuf[0];
    #pragma unroll
    for (int w = 1; w < 8; w++) s2 += rbuf[w];
    float rstd = rsqrtf(s2 * (1.f / DD) + 1e-5f);

    #pragma unroll
    for (int j = 0; j < 3; j++) {
        int c = tid * 3 + j;
        float u = (v[j] - mean) * rstd * g[c] + bb[c];
        orow[c] = u;
        orow2[c] = __float2half_rn(u);
    }
}

// ---------------- driver ----------------
extern "C" void kernel_launch(void* const* d_in, const int* in_sizes, int n_in,
                              void* d_out, int out_size)
{
    const int*   ids  = (const int*)  d_in[0];
    const int*   mask = (const int*)  d_in[1];
    const float* emb  = (const float*)d_in[2];
    const float* pe   = (const float*)d_in[3];
    const float* Wq   = (const float*)d_in[4];
    const float* Wk   = (const float*)d_in[5];
    const float* Wv   = (const float*)d_in[6];
    const float* Wo   = (const float*)d_in[7];
    const float* ln1g = (const float*)d_in[8];
    const float* ln1b = (const float*)d_in[9];
    const float* ln2g = (const float*)d_in[10];
    const float* ln2b = (const float*)d_in[11];
    const float* W1   = (const float*)d_in[12];
    const float* b1   = (const float*)d_in[13];
    const float* W2   = (const float*)d_in[14];
    const float* b2   = (const float*)d_in[15];
    const float* lnfg = (const float*)d_in[16];
    const float* lnfb = (const float*)d_in[17];
    const float* Wout = (const float*)d_in[18];
    const float* bout = (const float*)d_in[19];
    float* out = (float*)d_out;

    float *x, *tmp, *tmp2;
    __half *xr, *qkv, *ctx, *h, *vti;
    __half *wqi, *wki, *wvi, *woi, *w1i, *w2i, *wpi;
    cudaGetSymbolAddress((void**)&x,    g_x);
    cudaGetSymbolAddress((void**)&xr,   g_xr);
    cudaGetSymbolAddress((void**)&qkv,  g_qkv);
    cudaGetSymbolAddress((void**)&ctx,  g_ctx);
    cudaGetSymbolAddress((void**)&tmp,  g_tmp);
    cudaGetSymbolAddress((void**)&tmp2, g_tmp2);
    cudaGetSymbolAddress((void**)&h,    g_h);
    cudaGetSymbolAddress((void**)&vti,  g_vti);
    cudaGetSymbolAddress((void**)&wqi,  g_wqi);
    cudaGetSymbolAddress((void**)&wki,  g_wki);
    cudaGetSymbolAddress((void**)&wvi,  g_wvi);
    cudaGetSymbolAddress((void**)&woi,  g_woi);
    cudaGetSymbolAddress((void**)&w1i,  g_w1i);
    cudaGetSymbolAddress((void**)&w2i,  g_w2i);
    cudaGetSymbolAddress((void**)&wpi,  g_wpi);

    __half* q = qkv;
    __half* k = qkv + (size_t)NT * DD;
    __half* v = qkv + (size_t)2 * NT * DD;

    cudaFuncSetAttribute(k_fattn,   cudaFuncAttributeMaxDynamicSharedMemorySize, FA_SMEM);
    cudaFuncSetAttribute(k_gmma,    cudaFuncAttributeMaxDynamicSharedMemorySize, GM_SMEM);
    cudaFuncSetAttribute(k_gmma_m,  cudaFuncAttributeMaxDynamicSharedMemorySize, GM_SMEM);
    cudaFuncSetAttribute(k_gmma_sk, cudaFuncAttributeMaxDynamicSharedMemorySize, GM_SMEM);
    cudaFuncSetAttribute(k_qkv,     cudaFuncAttributeMaxDynamicSharedMemorySize, GM_SMEM);

    k_ilv<<<dim3(DD/64, DD/32, NL), 256>>>(Wq, wqi, DD, DD, DD);
    k_ilv<<<dim3(DD/64, DD/32, NL), 256>>>(Wk, wki, DD, DD, DD);
    k_ilv<<<dim3(DD/64, DD/32, NL), 256>>>(Wv, wvi, DD, DD, DD);
    k_ilv<<<dim3(DD/64, DD/32, NL), 256>>>(Wo, woi, DD, DD, DD);
    k_ilv<<<dim3(DD/64, FF/32, NL), 256>>>(W1, w1i, DD, FF, FF);
    k_ilv<<<dim3(FF/64, DD/32, NL), 256>>>(W2, w2i, FF, DD, DD);
    k_ilv<<<dim3(DD/64, NVP/32, 1), 256>>>(Wout, wpi, DD, NV, NVP);

    k_embed<<<(NT * DD + 255) / 256, 256>>>(ids, emb, pe, x, xr);

    dim3 gQKV(DD / 128, NT / 128, 3);
    dim3 gF(FF / 128, NT / 128);
    dim3 gSK(DD / 128, NT / 128, 2);
    dim3 gV(NT / 128, NVP / 128);
    dim3 gA(SQ / 128, BB * NH);
    dim3 gVI(SQ / 64, BB * NH);

    for (int l = 0; l < NL; l++) {
        size_t od = (size_t)l * DD * DD;
        size_t of = (size_t)l * DD * FF;

        k_qkv<<<gQKV, 128, GM_SMEM>>>(xr, wqi + od, wki + od, wvi + od, qkv);
        k_vilv<<<gVI, 256>>>(v, vti);

        k_fattn<<<gA, 256, FA_SMEM>>>(q, k, vti, mask, ctx);

        k_gmma_sk<<<gSK, 128, GM_SMEM>>>(ctx, woi + od, nullptr, tmp, tmp2,
                                         DD, DD, DD, DD / 2);
        k_addln3<<<NT, 256>>>(x, tmp, tmp2, ln1g + (size_t)l * DD, ln1b + (size_t)l * DD, x, xr);

        k_gmma<<<gF, 128, GM_SMEM>>>(xr, w1i + of, b1 + (size_t)l * FF, nullptr, h,
                                     FF, FF, DD, 1);

        k_gmma_sk<<<gSK, 128, GM_SMEM>>>(h, w2i + of, b2 + (size_t)l * DD, tmp, tmp2,
                                         DD, DD, FF, FF / 2);
        k_addln3<<<NT, 256>>>(x, tmp, tmp2, ln2g + (size_t)l * DD, ln2b + (size_t)l * DD, x, xr);
    }

    k_addln3<<<NT, 256>>>(x, nullptr, nullptr, lnfg, lnfb, x, xr);

    k_gmma_m<<<gV, 128, GM_SMEM>>>(xr, wpi, bout, out, NV, NVP, DD);
}

// round 13
// speedup vs baseline: 1.1353x; 1.1353x over previous
#include <cuda_runtime.h>
#include <cuda_fp16.h>
#include <math.h>
#include <stdint.h>

#define BB 2
#define SQ 1024
#define DD 768
#define NH 12
#define DK 64
#define FF 3072
#define NL 12
#define NV 50257
#define NVP 50432
#define NT (BB*SQ)

// ---------------- scratch (allocation-free: __device__ globals) ----------------
__device__ float  g_x   [NT*DD];
__device__ __half g_xr  [NT*DD];
__device__ __half g_qkv [2*NT*DD];               // Q, K slabs
__device__ __half g_ctx [NT*DD];
__device__ float  g_tmp [NT*DD];
__device__ float  g_tmp2[NT*DD];
__device__ __half g_h   [NT*FF];
__device__ __half g_vti [(size_t)BB*NH*SQ*DK];   // interleaved V (written by k_qkv z=2)
// pair-interleaved ([k/16][n][16 halves]) fp16 weights
__device__ __half g_wqi[NL*DD*DD];
__device__ __half g_wki[NL*DD*DD];
__device__ __half g_wvi[NL*DD*DD];
__device__ __half g_woi[NL*DD*DD];
__device__ __half g_w1i[(size_t)NL*DD*FF];
__device__ __half g_w2i[(size_t)NL*FF*DD];
__device__ __half g_wpi[(size_t)DD*NVP];

// ---------------- helpers ----------------
__device__ __forceinline__ void mma_f16(float* c, const unsigned* a, const unsigned* b) {
    asm volatile(
        "mma.sync.aligned.m16n8k16.row.col.f32.f16.f16.f32 "
        "{%0,%1,%2,%3}, {%4,%5,%6,%7}, {%8,%9}, {%0,%1,%2,%3};"
        : "+f"(c[0]), "+f"(c[1]), "+f"(c[2]), "+f"(c[3])
        : "r"(a[0]), "r"(a[1]), "r"(a[2]), "r"(a[3]), "r"(b[0]), "r"(b[1]));
}

__device__ __forceinline__ float gelu_f(float v) {
    return 0.5f * v * (1.f + erff(v * 0.70710678118654752f));
}

__device__ __forceinline__ uint32_t smem_u32(const void* p) {
    uint32_t a;
    asm("{ .reg .u64 t; cvta.to.shared.u64 t, %1; cvt.u32.u64 %0, t; }" : "=r"(a) : "l"(p));
    return a;
}
__device__ __forceinline__ void cpa16(uint32_t saddr, const void* g) {
    asm volatile("cp.async.cg.shared.global [%0], [%1], 16;" :: "r"(saddr), "l"(g));
}

// ---------------- embedding (fp32 x + fp16 xr) ----------------
__global__ void k_embed(const int* __restrict__ ids, const float* __restrict__ emb,
                        const float* __restrict__ pe, float* __restrict__ x,
                        __half* __restrict__ xr)
{
    int i = blockIdx.x * 256 + threadIdx.x;
    if (i >= NT * DD) return;
    int t = i / DD;
    int d = i - t * DD;
    int s = t % SQ;
    float v = emb[(size_t)ids[t] * DD + d] + pe[(size_t)s * DD + d];
    x[i] = v;
    xr[i] = __float2half_rn(v);
}

// ---------------- interleave + fp16 weights: out[k/16][n][16h] pair order ----------------
__global__ void k_ilv(const float* __restrict__ in, __half* __restrict__ out,
                      int Kd, int Nd, int Nout)
{
    __shared__ float sm[64][33];
    int z = blockIdx.z;
    in  += (size_t)z * Kd * Nd;
    out += (size_t)z * Kd * Nout;
    int kblk = blockIdx.x * 64;
    int n0 = blockIdx.y * 32;
    int tid = threadIdx.x;
    int tx = tid & 31, ty = tid >> 5;

    #pragma unroll
    for (int it = 0; it < 8; it++) {
        int kl = ty + it * 8;
        int n = n0 + tx;
        sm[kl][tx] = (n < Nd) ? in[(size_t)(kblk + kl) * Nd + n] : 0.f;
    }
    __syncthreads();
    #pragma unroll
    for (int it = 0; it < 4; it++) {
        int idx = tid + it * 256;
        int kb_l = idx >> 8;
        int rem = idx & 255;
        int n_l = rem >> 3;
        int pos = rem & 7;
        int i = (pos & 1) ? (pos >> 1) + 4 : (pos >> 1);
        int k_l = kb_l * 16 + 2 * i;
        __half2 hv = __floats2half2_rn(sm[k_l][n_l], sm[k_l + 1][n_l]);
        *(__half2*)&out[(((size_t)(kblk >> 4) + kb_l) * Nout + n0 + n_l) * 16 + pos * 2] = hv;
    }
}

// =====================================================================
// fp16 MMA GEMM core (R11 config: 256 threads, 8 warps 2m x 4n, warp 64x32)
// CTA 128x128, BK=64, double-buffered. A reg-prefetch -> pair-interleave
// (stride 40 u32); B pre-interleaved gmem -> cp.async.
// Output modes: Vt (interleaved V), Ch (half), C (float).
// =====================================================================
#define GM_SMEM ((size_t)18432 * 4)

__device__ __forceinline__ void gmma_core(
    const __half* __restrict__ A, const __half* __restrict__ B,
    const float* __restrict__ bias, float* __restrict__ C, __half* __restrict__ Ch,
    __half* __restrict__ Vt,
    int N, int ldb, int lda, int Klen, int koff, int act,
    int m0, int n0, uint32_t* sm)
{
    uint32_t* As0 = sm;
    uint32_t* Bs0 = sm + 5120;
    uint32_t* As1 = sm + 9216;
    uint32_t* Bs1 = sm + 14336;

    int tid = threadIdx.x;
    int lane = tid & 31, wid = tid >> 5;
    int wm = (wid >> 2) << 6;
    int wn = (wid & 3) << 5;
    int g = lane >> 2, tig = lane & 3;

    int aRow = tid >> 1, aSel = tid & 1;
    int bkb = tid >> 6;
    int bn  = tid & 63;

    const __half* Ap = A + (size_t)(m0 + aRow) * lda + koff + aSel * 32;
    const __half* Bp = B + ((size_t)((koff >> 4) + bkb) * ldb + n0 + bn) * 16;
    uint32_t b0a = smem_u32(Bs0 + bkb * 1024 + bn * 8);
    uint32_t b1a = smem_u32(Bs1 + bkb * 1024 + bn * 8);

    const int S = Klen >> 6;
    const size_t bstep = (size_t)4 * ldb * 16;

    cpa16(b0a, Bp);               cpa16(b0a + 16, Bp + 8);
    cpa16(b0a + 2048, Bp + 1024); cpa16(b0a + 2064, Bp + 1032);
    asm volatile("cp.async.commit_group;" ::: "memory");
    uint4 ra[4];
    #pragma unroll
    for (int i = 0; i < 4; i++) ra[i] = *(const uint4*)(Ap + 8 * i);

    float acc[4][4][4] = {};

    for (int s = 0; s < S; s++) {
        int buf = s & 1;
        uint32_t* As = buf ? As1 : As0;
        uint32_t* Bs = buf ? Bs1 : Bs0;

        {
            uint32_t* dst = As + aRow * 40 + aSel * 16;
            *(uint4*)(dst)      = make_uint4(ra[0].x, ra[1].x, ra[0].y, ra[1].y);
            *(uint4*)(dst + 4)  = make_uint4(ra[0].z, ra[1].z, ra[0].w, ra[1].w);
            *(uint4*)(dst + 8)  = make_uint4(ra[2].x, ra[3].x, ra[2].y, ra[3].y);
            *(uint4*)(dst + 12) = make_uint4(ra[2].z, ra[3].z, ra[2].w, ra[3].w);
        }

        if (s + 1 < S) {
            const __half* Ap2 = Ap + (s + 1) * 64;
            #pragma unroll
            for (int i = 0; i < 4; i++) ra[i] = *(const uint4*)(Ap2 + 8 * i);
            const __half* Bp2 = Bp + (size_t)(s + 1) * bstep;
            uint32_t ba = buf ? b0a : b1a;
            cpa16(ba, Bp2);               cpa16(ba + 16, Bp2 + 8);
            cpa16(ba + 2048, Bp2 + 1024); cpa16(ba + 2064, Bp2 + 1032);
            asm volatile("cp.async.commit_group;" ::: "memory");
            asm volatile("cp.async.wait_group 1;" ::: "memory");
        } else {
            asm volatile("cp.async.wait_group 0;" ::: "memory");
        }
        __syncthreads();

        #pragma unroll
        for (int kb = 0; kb < 4; kb++) {
            unsigned af[4][4], bf[4][2];
            #pragma unroll
            for (int mt = 0; mt < 4; mt++) {
                int r = wm + mt * 16 + g;
                uint2 pa = *(const uint2*)(As + r * 40 + kb * 8 + 2 * tig);
                uint2 pb = *(const uint2*)(As + (r + 8) * 40 + kb * 8 + 2 * tig);
                af[mt][0] = pa.x; af[mt][2] = pa.y;
                af[mt][1] = pb.x; af[mt][3] = pb.y;
            }
            #pragma unroll
            for (int nt = 0; nt < 4; nt++) {
                int c = wn + nt * 8 + g;
                uint2 pk = *(const uint2*)(Bs + kb * 1024 + c * 8 + 2 * tig);
                bf[nt][0] = pk.x; bf[nt][1] = pk.y;
            }
            #pragma unroll
            for (int mt = 0; mt < 4; mt++)
                #pragma unroll
                for (int nt = 0; nt < 4; nt++)
                    mma_f16(acc[mt][nt], af[mt], bf[nt]);
        }
        __syncthreads();
    }

    const bool fastC = (n0 + 128 <= N) && ((N & 3) == 0);
    #pragma unroll
    for (int mt = 0; mt < 4; mt++) {
        #pragma unroll
        for (int nt = 0; nt < 4; nt++) {
            int row = m0 + wm + mt * 16 + g;
            int col = n0 + wn + nt * 8 + 2 * tig;
            float c0 = acc[mt][nt][0], c1 = acc[mt][nt][1];
            float c2 = acc[mt][nt][2], c3 = acc[mt][nt][3];
            if (Vt) {
                // interleaved V epilogue: layout [bh][kb][d][16h], pair order.
                // t16(row)=g, t16(row+8)=g+8 -> offs 4*(g>>1)+(g&1), +2.
                int b_ = row >> 10;          // row / SQ
                int s_ = row & (SQ - 1);
                int h_ = col >> 6;
                int d_ = col & 63;
                int bh_ = b_ * NH + h_;
                int kb_ = s_ >> 4;
                uint32_t off = 4 * (g >> 1) + (g & 1);
                __half* basep = Vt + (size_t)bh_ * SQ * DK + ((size_t)(kb_ * 64 + d_) << 4);
                basep[off]          = __float2half_rn(c0);
                basep[off + 2]      = __float2half_rn(c2);
                basep[16 + off]     = __float2half_rn(c1);
                basep[16 + off + 2] = __float2half_rn(c3);
            } else if (Ch) {
                float b0 = bias ? bias[col] : 0.f;
                float b1 = bias ? bias[col + 1] : 0.f;
                c0 += b0; c1 += b1; c2 += b0; c3 += b1;
                if (act) { c0 = gelu_f(c0); c1 = gelu_f(c1); c2 = gelu_f(c2); c3 = gelu_f(c3); }
                *(__half2*)&Ch[(size_t)row * N + col]       = __floats2half2_rn(c0, c1);
                *(__half2*)&Ch[(size_t)(row + 8) * N + col] = __floats2half2_rn(c2, c3);
            } else if (fastC) {
                float b0 = bias ? bias[col] : 0.f;
                float b1 = bias ? bias[col + 1] : 0.f;
                c0 += b0; c1 += b1; c2 += b0; c3 += b1;
                if (act) { c0 = gelu_f(c0); c1 = gelu_f(c1); c2 = gelu_f(c2); c3 = gelu_f(c3); }
                *(float2*)&C[(size_t)row * N + col]       = make_float2(c0, c1);
                *(float2*)&C[(size_t)(row + 8) * N + col] = make_float2(c2, c3);
            } else {
                if (col < N) {
                    float b0 = bias ? bias[col] : 0.f;
                    float u0 = c0 + b0, u2 = c2 + b0;
                    if (act) { u0 = gelu_f(u0); u2 = gelu_f(u2); }
                    C[(size_t)row * N + col] = u0;
                    C[(size_t)(row + 8) * N + col] = u2;
                }
                if (col + 1 < N) {
                    float b1 = bias ? bias[col + 1] : 0.f;
                    float u1 = c1 + b1, u3 = c3 + b1;
                    if (act) { u1 = gelu_f(u1); u3 = gelu_f(u3); }
                    C[(size_t)row * N + col + 1] = u1;
                    C[(size_t)(row + 8) * N + col + 1] = u3;
                }
            }
        }
    }
}

__global__ void __launch_bounds__(256, 2)
k_gmma(const __half* __restrict__ A, const __half* __restrict__ B,
       const float* __restrict__ bias, float* __restrict__ C, __half* __restrict__ Ch,
       int N, int ldb, int K, int act)
{
    extern __shared__ uint32_t smu[];
    gmma_core(A, B, bias, C, Ch, nullptr, N, ldb, K, K, 0, act,
              blockIdx.y * 128, blockIdx.x * 128, smu);
}

__global__ void __launch_bounds__(256, 2)
k_gmma_m(const __half* __restrict__ A, const __half* __restrict__ B,
         const float* __restrict__ bias, float* __restrict__ C,
         int N, int ldb, int K)
{
    extern __shared__ uint32_t smu[];
    gmma_core(A, B, bias, C, nullptr, nullptr, N, ldb, K, K, 0, 0,
              blockIdx.x * 128, blockIdx.y * 128, smu);
}

__global__ void __launch_bounds__(256, 2)
k_gmma_sk(const __half* __restrict__ A, const __half* __restrict__ B,
          const float* __restrict__ bias, float* __restrict__ CA,
          float* __restrict__ CB, int N, int ldb, int lda, int Khalf)
{
    extern __shared__ uint32_t smu[];
    int z = blockIdx.z;
    float* C = z ? CB : CA;
    const float* bz = z ? nullptr : bias;
    gmma_core(A, B, bz, C, nullptr, nullptr, N, ldb, lda, Khalf, z * Khalf, 0,
              blockIdx.y * 128, blockIdx.x * 128, smu);
}

// fused QKV: z=0,1 -> half slabs; z=2 -> interleaved V
__global__ void __launch_bounds__(256, 2)
k_qkv(const __half* __restrict__ X, const __half* __restrict__ Wq,
      const __half* __restrict__ Wk, const __half* __restrict__ Wv,
      __half* __restrict__ QK, __half* __restrict__ Vt)
{
    extern __shared__ uint32_t smu[];
    int z = blockIdx.z;
    const __half* W = (z == 0) ? Wq : (z == 1) ? Wk : Wv;
    __half* O = (z < 2) ? (QK + (size_t)z * NT * DD) : nullptr;
    __half* Vo = (z == 2) ? Vt : nullptr;
    gmma_core(X, W, nullptr, nullptr, O, Vo, DD, DD, DD, DD, 0, 0,
              blockIdx.y * 128, blockIdx.x * 128, smu);
}

// =====================================================================
// Flash attention, fp16 m16n8k16 (unchanged from R11)
// =====================================================================
#define FA_SMEM (14912 * 4)

__global__ void __launch_bounds__(256, 2)
k_fattn(const __half* __restrict__ Q, const __half* __restrict__ K,
        const __half* __restrict__ Vt, const int* __restrict__ mask,
        __half* __restrict__ ctx)
{
    extern __shared__ uint32_t smu[];
    uint32_t* Qs = smu;
    uint32_t* Ks = smu + 5120;
    uint32_t* Vs = smu + 7680;
    uint32_t* Ps = smu + 9728;
    float* msk = (float*)(smu + 14848);

    int bh = blockIdx.y;
    int b = bh / NH, h = bh - b * NH;
    int i0 = blockIdx.x * 128;

    const __half* qb = Q + (size_t)b * SQ * DD + h * DK;
    const __half* kbp = K + (size_t)b * SQ * DD + h * DK;
    const __half* vth = Vt + (size_t)bh * SQ * DK;
    __half* cb = ctx + (size_t)b * SQ * DD + h * DK;
    const int* mrow = mask + (size_t)b * SQ;

    int tid = threadIdx.x;
    int lane = tid & 31, w = tid >> 5;
    int g = lane >> 2, tig = lane & 3;
    int wr = w * 16;

    {
        int r = tid >> 1, sel = tid & 1;
        const __half* qp = qb + (size_t)(i0 + r) * DD + sel * 32;
        uint4 a0 = *(const uint4*)qp;
        uint4 a1 = *(const uint4*)(qp + 8);
        uint4 a2 = *(const uint4*)(qp + 16);
        uint4 a3 = *(const uint4*)(qp + 24);
        uint32_t* dst = Qs + r * 40 + sel * 16;
        *(uint4*)(dst)      = make_uint4(a0.x, a1.x, a0.y, a1.y);
        *(uint4*)(dst + 4)  = make_uint4(a0.z, a1.z, a0.w, a1.w);
        *(uint4*)(dst + 8)  = make_uint4(a2.x, a3.x, a2.y, a3.y);
        *(uint4*)(dst + 12) = make_uint4(a2.z, a3.z, a2.w, a3.w);
    }

    float oacc[8][4] = {};
    float mr0 = -1e30f, mr1 = -1e30f, l0 = 0.f, l1 = 0.f;

    for (int kt = 0; kt < SQ; kt += 64) {
        __syncthreads();
        {
            uint32_t dsta = smem_u32(Vs) + tid * 32;
            const __half* src = vth + (size_t)(kt >> 4) * 1024 + tid * 16;
            cpa16(dsta, src);
            cpa16(dsta + 16, src + 8);
            asm volatile("cp.async.commit_group;" ::: "memory");
        }
        {
            int r = tid >> 2, qk = tid & 3;
            const __half* kp = kbp + (size_t)(kt + r) * DD + qk * 16;
            uint4 a0 = *(const uint4*)kp;
            uint4 a1 = *(const uint4*)(kp + 8);
            uint32_t* dst = Ks + r * 40 + qk * 8;
            *(uint4*)(dst)     = make_uint4(a0.x, a1.x, a0.y, a1.y);
            *(uint4*)(dst + 4) = make_uint4(a0.z, a1.z, a0.w, a1.w);
        }
        if (tid < 64) msk[tid] = (mrow[kt + tid] == 0) ? -1e9f : 0.f;
        asm volatile("cp.async.wait_group 0;" ::: "memory");
        __syncthreads();

        float sacc[8][4] = {};
        #pragma unroll
        for (int m = 0; m < 4; m++) {
            unsigned af[4];
            {
                uint2 pa = *(const uint2*)(Qs + (wr + g) * 40 + m * 8 + 2 * tig);
                uint2 pb = *(const uint2*)(Qs + (wr + g + 8) * 40 + m * 8 + 2 * tig);
                af[0] = pa.x; af[2] = pa.y;
                af[1] = pb.x; af[3] = pb.y;
            }
            #pragma unroll
            for (int j = 0; j < 8; j++) {
                uint2 pk = *(const uint2*)(Ks + (j * 8 + g) * 40 + m * 8 + 2 * tig);
                unsigned bf[2] = { pk.x, pk.y };
                mma_f16(sacc[j], af, bf);
            }
        }

        float tm0 = -1e30f, tm1 = -1e30f;
        #pragma unroll
        for (int j = 0; j < 8; j++) {
            int c = j * 8 + 2 * tig;
            float a0 = msk[c], a1 = msk[c + 1];
            sacc[j][0] = sacc[j][0] * 0.125f + a0;
            sacc[j][1] = sacc[j][1] * 0.125f + a1;
            sacc[j][2] = sacc[j][2] * 0.125f + a0;
            sacc[j][3] = sacc[j][3] * 0.125f + a1;
            tm0 = fmaxf(tm0, fmaxf(sacc[j][0], sacc[j][1]));
            tm1 = fmaxf(tm1, fmaxf(sacc[j][2], sacc[j][3]));
        }
        tm0 = fmaxf(tm0, __shfl_xor_sync(0xffffffffu, tm0, 1));
        tm0 = fmaxf(tm0, __shfl_xor_sync(0xffffffffu, tm0, 2));
        tm1 = fmaxf(tm1, __shfl_xor_sync(0xffffffffu, tm1, 1));
        tm1 = fmaxf(tm1, __shfl_xor_sync(0xffffffffu, tm1, 2));

        float mn0 = fmaxf(mr0, tm0), mn1 = fmaxf(mr1, tm1);
        float al0 = __expf(mr0 - mn0), al1 = __expf(mr1 - mn1);

        __syncwarp();
        float ts0 = 0.f, ts1 = 0.f;
        #pragma unroll
        for (int j = 0; j < 8; j++) {
            float p0v = __expf(sacc[j][0] - mn0);
            float p1v = __expf(sacc[j][1] - mn0);
            float p2v = __expf(sacc[j][2] - mn1);
            float p3v = __expf(sacc[j][3] - mn1);
            ts0 += p0v + p1v;
            ts1 += p2v + p3v;
            int m = j >> 1;
            int pi = (j & 1) * 4 + tig;
            int pos = 2 * (pi & 3) + (pi >> 2);
            *(__half2*)(Ps + (wr + g) * 40 + m * 8 + pos)     = __floats2half2_rn(p0v, p1v);
            *(__half2*)(Ps + (wr + g + 8) * 40 + m * 8 + pos) = __floats2half2_rn(p2v, p3v);
        }
        ts0 += __shfl_xor_sync(0xffffffffu, ts0, 1);
        ts0 += __shfl_xor_sync(0xffffffffu, ts0, 2);
        ts1 += __shfl_xor_sync(0xffffffffu, ts1, 1);
        ts1 += __shfl_xor_sync(0xffffffffu, ts1, 2);
        l0 = l0 * al0 + ts0;
        l1 = l1 * al1 + ts1;
        mr0 = mn0; mr1 = mn1;

        #pragma unroll
        for (int j = 0; j < 8; j++) {
            oacc[j][0] *= al0; oacc[j][1] *= al0;
            oacc[j][2] *= al1; oacc[j][3] *= al1;
        }
        __syncwarp();

        #pragma unroll
        for (int m = 0; m < 4; m++) {
            unsigned af[4];
            {
                uint2 pa = *(const uint2*)(Ps + (wr + g) * 40 + m * 8 + 2 * tig);
                uint2 pb = *(const uint2*)(Ps + (wr + g + 8) * 40 + m * 8 + 2 * tig);
                af[0] = pa.x; af[2] = pa.y;
                af[1] = pb.x; af[3] = pb.y;
            }
            #pragma unroll
            for (int j = 0; j < 8; j++) {
                uint2 pk = *(const uint2*)(Vs + m * 512 + (j * 8 + g) * 8 + 2 * tig);
                unsigned bf[2] = { pk.x, pk.y };
                mma_f16(oacc[j], af, bf);
            }
        }
    }

    float il0 = 1.f / l0, il1 = 1.f / l1;
    int r0 = i0 + wr + g;
    #pragma unroll
    for (int j = 0; j < 8; j++) {
        int c = j * 8 + 2 * tig;
        *(__half2*)&cb[(size_t)r0 * DD + c] =
            __floats2half2_rn(oacc[j][0] * il0, oacc[j][1] * il0);
        *(__half2*)&cb[(size_t)(r0 + 8) * DD + c] =
            __floats2half2_rn(oacc[j][2] * il1, oacc[j][3] * il1);
    }
}

// ---------------- LayerNorm(x (+ ra) (+ rb)); outputs fp32 + fp16 ----------------
__global__ void k_addln3(const float* __restrict__ X, const float* __restrict__ RA,
                         const float* __restrict__ RB,
                         const float* __restrict__ g, const float* __restrict__ bb,
                         float* __restrict__ O, __half* __restrict__ Or)
{
    int r = blockIdx.x;
    const float* xrow = X + (size_t)r * DD;
    const float* ra = RA ? (RA + (size_t)r * DD) : nullptr;
    const float* rbp = RB ? (RB + (size_t)r * DD) : nullptr;
    float* orow = O + (size_t)r * DD;
    __half* orow2 = Or + (size_t)r * DD;

    int tid = threadIdx.x;
    __shared__ float rbuf[8];

    float v[3];
    float s = 0.f;
    #pragma unroll
    for (int j = 0; j < 3; j++) {
        int c = tid * 3 + j;
        float x = xrow[c];
        if (ra) x += ra[c];
        if (rbp) x += rbp[c];
        v[j] = x;
        s += x;
    }
    #pragma unroll
    for (int o = 16; o; o >>= 1) s += __shfl_xor_sync(0xffffffffu, s, o);
    __syncthreads();
    if ((tid & 31) == 0) rbuf[tid >> 5] = s;
    __syncthreads();
    s = rbuf[0];
    #pragma unroll
    for (int w = 1; w < 8; w++) s += rbuf[w];
    float mean = s * (1.f / DD);

    float s2 = 0.f;
    #pragma unroll
    for (int j = 0; j < 3; j++) { float d = v[j] - mean; s2 += d * d; }
    #pragma unroll
    for (int o = 16; o; o >>= 1) s2 += __shfl_xor_sync(0xffffffffu, s2, o);
    __syncthreads();
    if ((tid & 31) == 0) rbuf[tid >> 5] = s2;
    __syncthreads();
    s2 = rbuf[0];
    #pragma unroll
    for (int w = 1; w < 8; w++) s2 += rbuf[w];
    float rstd = rsqrtf(s2 * (1.f / DD) + 1e-5f);

    #pragma unroll
    for (int j = 0; j < 3; j++) {
        int c = tid * 3 + j;
        float u = (v[j] - mean) * rstd * g[c] + bb[c];
        orow[c] = u;
        orow2[c] = __float2half_rn(u);
    }
}

// ---------------- driver ----------------
extern "C" void kernel_launch(void* const* d_in, const int* in_sizes, int n_in,
                              void* d_out, int out_size)
{
    const int*   ids  = (const int*)  d_in[0];
    const int*   mask = (const int*)  d_in[1];
    const float* emb  = (const float*)d_in[2];
    const float* pe   = (const float*)d_in[3];
    const float* Wq   = (const float*)d_in[4];
    const float* Wk   = (const float*)d_in[5];
    const float* Wv   = (const float*)d_in[6];
    const float* Wo   = (const float*)d_in[7];
    const float* ln1g = (const float*)d_in[8];
    const float* ln1b = (const float*)d_in[9];
    const float* ln2g = (const float*)d_in[10];
    const float* ln2b = (const float*)d_in[11];
    const float* W1   = (const float*)d_in[12];
    const float* b1   = (const float*)d_in[13];
    const float* W2   = (const float*)d_in[14];
    const float* b2   = (const float*)d_in[15];
    const float* lnfg = (const float*)d_in[16];
    const float* lnfb = (const float*)d_in[17];
    const float* Wout = (const float*)d_in[18];
    const float* bout = (const float*)d_in[19];
    float* out = (float*)d_out;

    float *x, *tmp, *tmp2;
    __half *xr, *qkv, *ctx, *h, *vti;
    __half *wqi, *wki, *wvi, *woi, *w1i, *w2i, *wpi;
    cudaGetSymbolAddress((void**)&x,    g_x);
    cudaGetSymbolAddress((void**)&xr,   g_xr);
    cudaGetSymbolAddress((void**)&qkv,  g_qkv);
    cudaGetSymbolAddress((void**)&ctx,  g_ctx);
    cudaGetSymbolAddress((void**)&tmp,  g_tmp);
    cudaGetSymbolAddress((void**)&tmp2, g_tmp2);
    cudaGetSymbolAddress((void**)&h,    g_h);
    cudaGetSymbolAddress((void**)&vti,  g_vti);
    cudaGetSymbolAddress((void**)&wqi,  g_wqi);
    cudaGetSymbolAddress((void**)&wki,  g_wki);
    cudaGetSymbolAddress((void**)&wvi,  g_wvi);
    cudaGetSymbolAddress((void**)&woi,  g_woi);
    cudaGetSymbolAddress((void**)&w1i,  g_w1i);
    cudaGetSymbolAddress((void**)&w2i,  g_w2i);
    cudaGetSymbolAddress((void**)&wpi,  g_wpi);

    __half* q = qkv;
    __half* k = qkv + (size_t)NT * DD;

    cudaFuncSetAttribute(k_fattn,   cudaFuncAttributeMaxDynamicSharedMemorySize, FA_SMEM);
    cudaFuncSetAttribute(k_gmma,    cudaFuncAttributeMaxDynamicSharedMemorySize, GM_SMEM);
    cudaFuncSetAttribute(k_gmma_m,  cudaFuncAttributeMaxDynamicSharedMemorySize, GM_SMEM);
    cudaFuncSetAttribute(k_gmma_sk, cudaFuncAttributeMaxDynamicSharedMemorySize, GM_SMEM);
    cudaFuncSetAttribute(k_qkv,     cudaFuncAttributeMaxDynamicSharedMemorySize, GM_SMEM);

    k_ilv<<<dim3(DD/64, DD/32, NL), 256>>>(Wq, wqi, DD, DD, DD);
    k_ilv<<<dim3(DD/64, DD/32, NL), 256>>>(Wk, wki, DD, DD, DD);
    k_ilv<<<dim3(DD/64, DD/32, NL), 256>>>(Wv, wvi, DD, DD, DD);
    k_ilv<<<dim3(DD/64, DD/32, NL), 256>>>(Wo, woi, DD, DD, DD);
    k_ilv<<<dim3(DD/64, FF/32, NL), 256>>>(W1, w1i, DD, FF, FF);
    k_ilv<<<dim3(FF/64, DD/32, NL), 256>>>(W2, w2i, FF, DD, DD);
    k_ilv<<<dim3(DD/64, NVP/32, 1), 256>>>(Wout, wpi, DD, NV, NVP);

    k_embed<<<(NT * DD + 255) / 256, 256>>>(ids, emb, pe, x, xr);

    dim3 gQKV(DD / 128, NT / 128, 3);
    dim3 gF(FF / 128, NT / 128);
    dim3 gSK(DD / 128, NT / 128, 2);
    dim3 gV(NT / 128, NVP / 128);
    dim3 gA(SQ / 128, BB * NH);

    for (int l = 0; l < NL; l++) {
        size_t od = (size_t)l * DD * DD;
        size_t of = (size_t)l * DD * FF;

        k_qkv<<<gQKV, 256, GM_SMEM>>>(xr, wqi + od, wki + od, wvi + od, qkv, vti);

        k_fattn<<<gA, 256, FA_SMEM>>>(q, k, vti, mask, ctx);

        k_gmma_sk<<<gSK, 256, GM_SMEM>>>(ctx, woi + od, nullptr, tmp, tmp2,
                                         DD, DD, DD, DD / 2);
        k_addln3<<<NT, 256>>>(x, tmp, tmp2, ln1g + (size_t)l * DD, ln1b + (size_t)l * DD, x, xr);

        k_gmma<<<gF, 256, GM_SMEM>>>(xr, w1i + of, b1 + (size_t)l * FF, nullptr, h,
                                     FF, FF, DD, 1);

        k_gmma_sk<<<gSK, 256, GM_SMEM>>>(h, w2i + of, b2 + (size_t)l * DD, tmp, tmp2,
                                         DD, DD, FF, FF / 2);
        k_addln3<<<NT, 256>>>(x, tmp, tmp2, ln2g + (size_t)l * DD, ln2b + (size_t)l * DD, x, xr);
    }

    k_addln3<<<NT, 256>>>(x, nullptr, nullptr, lnfg, lnfb, x, xr);

    k_gmma_m<<<gV, 256, GM_SMEM>>>(xr, wpi, bout, out, NV, NVP, DD);
}

// round 14
// speedup vs baseline: 1.1723x; 1.0326x over previous
#include <cuda_runtime.h>
#include <cuda_fp16.h>
#include <math.h>
#include <stdint.h>

#define BB 2
#define SQ 1024
#define DD 768
#define NH 12
#define DK 64
#define FF 3072
#define NL 12
#define NV 50257
#define NVP 50432
#define NT (BB*SQ)

// ---------------- scratch (allocation-free: __device__ globals) ----------------
// All fp16 activations are stored PAIR-INTERLEAVED per 16-k block:
// pair t (halves 2t,2t+1) of each block sits at slot (t<4 ? 2t : 2(t-4)+1).
__device__ float  g_x   [NT*DD];
__device__ __half g_xr  [NT*DD];
__device__ __half g_qkv [2*NT*DD];               // Q, K slabs (interleaved)
__device__ __half g_ctx [NT*DD];                 // interleaved
__device__ float  g_tmp [NT*DD];
__device__ float  g_tmp2[NT*DD];
__device__ __half g_h   [NT*FF];                 // interleaved
__device__ __half g_vti [(size_t)BB*NH*SQ*DK];   // interleaved V ([bh][kb][d][16h])
// pair-interleaved ([k/16][n][16 halves]) fp16 weights
__device__ __half g_wqi[NL*DD*DD];
__device__ __half g_wki[NL*DD*DD];
__device__ __half g_wvi[NL*DD*DD];
__device__ __half g_woi[NL*DD*DD];
__device__ __half g_w1i[(size_t)NL*DD*FF];
__device__ __half g_w2i[(size_t)NL*FF*DD];
__device__ __half g_wpi[(size_t)DD*NVP];

// ---------------- helpers ----------------
__device__ __forceinline__ void mma_f16(float* c, const unsigned* a, const unsigned* b) {
    asm volatile(
        "mma.sync.aligned.m16n8k16.row.col.f32.f16.f16.f32 "
        "{%0,%1,%2,%3}, {%4,%5,%6,%7}, {%8,%9}, {%0,%1,%2,%3};"
        : "+f"(c[0]), "+f"(c[1]), "+f"(c[2]), "+f"(c[3])
        : "r"(a[0]), "r"(a[1]), "r"(a[2]), "r"(a[3]), "r"(b[0]), "r"(b[1]));
}

__device__ __forceinline__ float gelu_f(float v) {
    return 0.5f * v * (1.f + erff(v * 0.70710678118654752f));
}

__device__ __forceinline__ uint32_t smem_u32(const void* p) {
    uint32_t a;
    asm("{ .reg .u64 t; cvta.to.shared.u64 t, %1; cvt.u32.u64 %0, t; }" : "=r"(a) : "l"(p));
    return a;
}
__device__ __forceinline__ void cpa16(uint32_t saddr, const void* g) {
    asm volatile("cp.async.cg.shared.global [%0], [%1], 16;" :: "r"(saddr), "l"(g));
}

// interleaved half-offset of even element c within its row
__device__ __forceinline__ int ilv_off(int c) {
    int pi = (c >> 1) & 7;
    int slot = (pi < 4) ? (pi << 1) : (((pi - 4) << 1) + 1);
    return (c & ~15) + slot * 2;
}

// ---------------- embedding (fp32 x + interleaved fp16 xr) ----------------
__global__ void k_embed(const int* __restrict__ ids, const float* __restrict__ emb,
                        const float* __restrict__ pe, float* __restrict__ x,
                        __half* __restrict__ xr)
{
    int idx = blockIdx.x * 256 + threadIdx.x;
    if (idx >= NT * DD / 2) return;
    int i = idx * 2;
    int t = i / DD;
    int d = i - t * DD;
    int s = t % SQ;
    const float* ep = emb + (size_t)ids[t] * DD + d;
    const float* pp = pe + (size_t)s * DD + d;
    float v0 = ep[0] + pp[0];
    float v1 = ep[1] + pp[1];
    x[i] = v0; x[i + 1] = v1;
    *(__half2*)&xr[(size_t)t * DD + ilv_off(d)] = __floats2half2_rn(v0, v1);
}

// ---------------- interleave + fp16 weights: out[k/16][n][16h] pair order ----------------
__global__ void k_ilv(const float* __restrict__ in, __half* __restrict__ out,
                      int Kd, int Nd, int Nout)
{
    __shared__ float sm[64][33];
    int z = blockIdx.z;
    in  += (size_t)z * Kd * Nd;
    out += (size_t)z * Kd * Nout;
    int kblk = blockIdx.x * 64;
    int n0 = blockIdx.y * 32;
    int tid = threadIdx.x;
    int tx = tid & 31, ty = tid >> 5;

    #pragma unroll
    for (int it = 0; it < 8; it++) {
        int kl = ty + it * 8;
        int n = n0 + tx;
        sm[kl][tx] = (n < Nd) ? in[(size_t)(kblk + kl) * Nd + n] : 0.f;
    }
    __syncthreads();
    #pragma unroll
    for (int it = 0; it < 4; it++) {
        int idx = tid + it * 256;
        int kb_l = idx >> 8;
        int rem = idx & 255;
        int n_l = rem >> 3;
        int pos = rem & 7;
        int i = (pos & 1) ? (pos >> 1) + 4 : (pos >> 1);
        int k_l = kb_l * 16 + 2 * i;
        __half2 hv = __floats2half2_rn(sm[k_l][n_l], sm[k_l + 1][n_l]);
        *(__half2*)&out[(((size_t)(kblk >> 4) + kb_l) * Nout + n0 + n_l) * 16 + pos * 2] = hv;
    }
}

// =====================================================================
// fp16 MMA GEMM core: 256 threads, 8 warps (2m x 4n), warp 64x32.
// CTA 128x128, BK=64, double-buffered. A AND B interleaved in gmem ->
// both loaded via cp.async (no reg round trip).
// =====================================================================
#define GM_SMEM ((size_t)18432 * 4)

__device__ __forceinline__ void gmma_core(
    const __half* __restrict__ A, const __half* __restrict__ B,
    const float* __restrict__ bias, float* __restrict__ C, __half* __restrict__ Ch,
    __half* __restrict__ Vt, int chIlv,
    int N, int ldb, int lda, int Klen, int koff, int act,
    int m0, int n0, uint32_t* sm)
{
    uint32_t* As0 = sm;
    uint32_t* Bs0 = sm + 5120;
    uint32_t* As1 = sm + 9216;
    uint32_t* Bs1 = sm + 14336;

    int tid = threadIdx.x;
    int lane = tid & 31, wid = tid >> 5;
    int wm = (wid >> 2) << 6;
    int wn = (wid & 3) << 5;
    int g = lane >> 2, tig = lane & 3;

    int aRow = tid >> 1, aSel = tid & 1;
    int bkb = tid >> 6;
    int bn  = tid & 63;

    const __half* ApB = A + (size_t)(m0 + aRow) * lda + koff + aSel * 32;
    const __half* Bp  = B + ((size_t)((koff >> 4) + bkb) * ldb + n0 + bn) * 16;
    uint32_t a0a = smem_u32(As0 + aRow * 40 + aSel * 16);
    uint32_t a1a = smem_u32(As1 + aRow * 40 + aSel * 16);
    uint32_t b0a = smem_u32(Bs0 + bkb * 1024 + bn * 8);
    uint32_t b1a = smem_u32(Bs1 + bkb * 1024 + bn * 8);

    const int S = Klen >> 6;
    const size_t bstep = (size_t)4 * ldb * 16;

    // prologue: stage 0 A + B via cp.async
    #pragma unroll
    for (int j = 0; j < 4; j++) cpa16(a0a + 16 * j, ApB + 8 * j);
    cpa16(b0a, Bp);               cpa16(b0a + 16, Bp + 8);
    cpa16(b0a + 2048, Bp + 1024); cpa16(b0a + 2064, Bp + 1032);
    asm volatile("cp.async.commit_group;" ::: "memory");

    float acc[4][4][4] = {};

    for (int s = 0; s < S; s++) {
        int buf = s & 1;
        uint32_t* As = buf ? As1 : As0;
        uint32_t* Bs = buf ? Bs1 : Bs0;

        if (s + 1 < S) {
            const __half* Ap2 = ApB + (s + 1) * 64;
            const __half* Bp2 = Bp + (size_t)(s + 1) * bstep;
            uint32_t aa = buf ? a0a : a1a;
            uint32_t ba = buf ? b0a : b1a;
            #pragma unroll
            for (int j = 0; j < 4; j++) cpa16(aa + 16 * j, Ap2 + 8 * j);
            cpa16(ba, Bp2);               cpa16(ba + 16, Bp2 + 8);
            cpa16(ba + 2048, Bp2 + 1024); cpa16(ba + 2064, Bp2 + 1032);
            asm volatile("cp.async.commit_group;" ::: "memory");
            asm volatile("cp.async.wait_group 1;" ::: "memory");
        } else {
            asm volatile("cp.async.wait_group 0;" ::: "memory");
        }
        __syncthreads();

        #pragma unroll
        for (int kb = 0; kb < 4; kb++) {
            unsigned af[4][4], bf[4][2];
            #pragma unroll
            for (int mt = 0; mt < 4; mt++) {
                int r = wm + mt * 16 + g;
                uint2 pa = *(const uint2*)(As + r * 40 + kb * 8 + 2 * tig);
                uint2 pb = *(const uint2*)(As + (r + 8) * 40 + kb * 8 + 2 * tig);
                af[mt][0] = pa.x; af[mt][2] = pa.y;
                af[mt][1] = pb.x; af[mt][3] = pb.y;
            }
            #pragma unroll
            for (int nt = 0; nt < 4; nt++) {
                int c = wn + nt * 8 + g;
                uint2 pk = *(const uint2*)(Bs + kb * 1024 + c * 8 + 2 * tig);
                bf[nt][0] = pk.x; bf[nt][1] = pk.y;
            }
            #pragma unroll
            for (int mt = 0; mt < 4; mt++)
                #pragma unroll
                for (int nt = 0; nt < 4; nt++)
                    mma_f16(acc[mt][nt], af[mt], bf[nt]);
        }
        __syncthreads();
    }

    const bool fastC = (n0 + 128 <= N) && ((N & 3) == 0);
    #pragma unroll
    for (int mt = 0; mt < 4; mt++) {
        #pragma unroll
        for (int nt = 0; nt < 4; nt++) {
            int row = m0 + wm + mt * 16 + g;
            int col = n0 + wn + nt * 8 + 2 * tig;
            float c0 = acc[mt][nt][0], c1 = acc[mt][nt][1];
            float c2 = acc[mt][nt][2], c3 = acc[mt][nt][3];
            if (Vt) {
                int b_ = row >> 10;
                int s_ = row & (SQ - 1);
                int h_ = col >> 6;
                int d_ = col & 63;
                int bh_ = b_ * NH + h_;
                int kb_ = s_ >> 4;
                uint32_t off = 4 * (g >> 1) + (g & 1);
                __half* basep = Vt + (size_t)bh_ * SQ * DK + ((size_t)(kb_ * 64 + d_) << 4);
                basep[off]          = __float2half_rn(c0);
                basep[off + 2]      = __float2half_rn(c2);
                basep[16 + off]     = __float2half_rn(c1);
                basep[16 + off + 2] = __float2half_rn(c3);
            } else if (Ch) {
                float b0 = bias ? bias[col] : 0.f;
                float b1 = bias ? bias[col + 1] : 0.f;
                c0 += b0; c1 += b1; c2 += b0; c3 += b1;
                if (act) { c0 = gelu_f(c0); c1 = gelu_f(c1); c2 = gelu_f(c2); c3 = gelu_f(c3); }
                int cadj = chIlv ? ilv_off(col) : col;
                *(__half2*)&Ch[(size_t)row * N + cadj]       = __floats2half2_rn(c0, c1);
                *(__half2*)&Ch[(size_t)(row + 8) * N + cadj] = __floats2half2_rn(c2, c3);
            } else if (fastC) {
                float b0 = bias ? bias[col] : 0.f;
                float b1 = bias ? bias[col + 1] : 0.f;
                c0 += b0; c1 += b1; c2 += b0; c3 += b1;
                if (act) { c0 = gelu_f(c0); c1 = gelu_f(c1); c2 = gelu_f(c2); c3 = gelu_f(c3); }
                *(float2*)&C[(size_t)row * N + col]       = make_float2(c0, c1);
                *(float2*)&C[(size_t)(row + 8) * N + col] = make_float2(c2, c3);
            } else {
                if (col < N) {
                    float b0 = bias ? bias[col] : 0.f;
                    float u0 = c0 + b0, u2 = c2 + b0;
                    if (act) { u0 = gelu_f(u0); u2 = gelu_f(u2); }
                    C[(size_t)row * N + col] = u0;
                    C[(size_t)(row + 8) * N + col] = u2;
                }
                if (col + 1 < N) {
                    float b1 = bias ? bias[col + 1] : 0.f;
                    float u1 = c1 + b1, u3 = c3 + b1;
                    if (act) { u1 = gelu_f(u1); u3 = gelu_f(u3); }
                    C[(size_t)row * N + col + 1] = u1;
                    C[(size_t)(row + 8) * N + col + 1] = u3;
                }
            }
        }
    }
}

__global__ void __launch_bounds__(256, 2)
k_gmma(const __half* __restrict__ A, const __half* __restrict__ B,
       const float* __restrict__ bias, float* __restrict__ C, __half* __restrict__ Ch,
       int N, int ldb, int K, int act, int chIlv)
{
    extern __shared__ uint32_t smu[];
    gmma_core(A, B, bias, C, Ch, nullptr, chIlv, N, ldb, K, K, 0, act,
              blockIdx.y * 128, blockIdx.x * 128, smu);
}

__global__ void __launch_bounds__(256, 2)
k_gmma_m(const __half* __restrict__ A, const __half* __restrict__ B,
         const float* __restrict__ bias, float* __restrict__ C,
         int N, int ldb, int K)
{
    extern __shared__ uint32_t smu[];
    gmma_core(A, B, bias, C, nullptr, nullptr, 0, N, ldb, K, K, 0, 0,
              blockIdx.x * 128, blockIdx.y * 128, smu);
}

__global__ void __launch_bounds__(256, 2)
k_gmma_sk(const __half* __restrict__ A, const __half* __restrict__ B,
          const float* __restrict__ bias, float* __restrict__ CA,
          float* __restrict__ CB, int N, int ldb, int lda, int Khalf)
{
    extern __shared__ uint32_t smu[];
    int z = blockIdx.z;
    float* C = z ? CB : CA;
    const float* bz = z ? nullptr : bias;
    gmma_core(A, B, bz, C, nullptr, nullptr, 0, N, ldb, lda, Khalf, z * Khalf, 0,
              blockIdx.y * 128, blockIdx.x * 128, smu);
}

// fused QKV: z=0,1 -> interleaved Q/K slabs; z=2 -> interleaved V
__global__ void __launch_bounds__(256, 2)
k_qkv(const __half* __restrict__ X, const __half* __restrict__ Wq,
      const __half* __restrict__ Wk, const __half* __restrict__ Wv,
      __half* __restrict__ QK, __half* __restrict__ Vt)
{
    extern __shared__ uint32_t smu[];
    int z = blockIdx.z;
    const __half* W = (z == 0) ? Wq : (z == 1) ? Wk : Wv;
    __half* O = (z < 2) ? (QK + (size_t)z * NT * DD) : nullptr;
    __half* Vo = (z == 2) ? Vt : nullptr;
    gmma_core(X, W, nullptr, nullptr, O, Vo, 1, DD, DD, DD, DD, 0, 0,
              blockIdx.y * 128, blockIdx.x * 128, smu);
}

// =====================================================================
// Flash attention: Q/K/V all interleaved in gmem -> cp.async copies.
// =====================================================================
#define FA_SMEM (14912 * 4)

__global__ void __launch_bounds__(256, 2)
k_fattn(const __half* __restrict__ Q, const __half* __restrict__ K,
        const __half* __restrict__ Vt, const int* __restrict__ mask,
        __half* __restrict__ ctx)
{
    extern __shared__ uint32_t smu[];
    uint32_t* Qs = smu;
    uint32_t* Ks = smu + 5120;
    uint32_t* Vs = smu + 7680;
    uint32_t* Ps = smu + 9728;
    float* msk = (float*)(smu + 14848);

    int bh = blockIdx.y;
    int b = bh / NH, h = bh - b * NH;
    int i0 = blockIdx.x * 128;

    const __half* qb = Q + (size_t)b * SQ * DD + h * DK;
    const __half* kbp = K + (size_t)b * SQ * DD + h * DK;
    const __half* vth = Vt + (size_t)bh * SQ * DK;
    __half* cb = ctx + (size_t)b * SQ * DD + h * DK;
    const int* mrow = mask + (size_t)b * SQ;

    int tid = threadIdx.x;
    int lane = tid & 31, w = tid >> 5;
    int g = lane >> 2, tig = lane & 3;
    int wr = w * 16;

    // Q tile: contiguous cp.async (interleaved gmem layout)
    {
        int r = tid >> 1, sel = tid & 1;
        uint32_t qa = smem_u32(Qs + r * 40 + sel * 16);
        const __half* qp = qb + (size_t)(i0 + r) * DD + sel * 32;
        #pragma unroll
        for (int j = 0; j < 4; j++) cpa16(qa + 16 * j, qp + 8 * j);
        // committed with first tile's group below
    }

    float oacc[8][4] = {};
    float mr0 = -1e30f, mr1 = -1e30f, l0 = 0.f, l1 = 0.f;

    for (int kt = 0; kt < SQ; kt += 64) {
        __syncthreads();
        {
            uint32_t dsta = smem_u32(Vs) + tid * 32;
            const __half* src = vth + (size_t)(kt >> 4) * 1024 + tid * 16;
            cpa16(dsta, src);
            cpa16(dsta + 16, src + 8);
        }
        {
            int r = tid >> 2, qk = tid & 3;
            uint32_t ka = smem_u32(Ks + r * 40 + qk * 8);
            const __half* kp = kbp + (size_t)(kt + r) * DD + qk * 16;
            cpa16(ka, kp);
            cpa16(ka + 16, kp + 8);
        }
        asm volatile("cp.async.commit_group;" ::: "memory");
        if (tid < 64) msk[tid] = (mrow[kt + tid] == 0) ? -1e9f : 0.f;
        asm volatile("cp.async.wait_group 0;" ::: "memory");
        __syncthreads();

        float sacc[8][4] = {};
        #pragma unroll
        for (int m = 0; m < 4; m++) {
            unsigned af[4];
            {
                uint2 pa = *(const uint2*)(Qs + (wr + g) * 40 + m * 8 + 2 * tig);
                uint2 pb = *(const uint2*)(Qs + (wr + g + 8) * 40 + m * 8 + 2 * tig);
                af[0] = pa.x; af[2] = pa.y;
                af[1] = pb.x; af[3] = pb.y;
            }
            #pragma unroll
            for (int j = 0; j < 8; j++) {
                uint2 pk = *(const uint2*)(Ks + (j * 8 + g) * 40 + m * 8 + 2 * tig);
                unsigned bf[2] = { pk.x, pk.y };
                mma_f16(sacc[j], af, bf);
            }
        }

        float tm0 = -1e30f, tm1 = -1e30f;
        #pragma unroll
        for (int j = 0; j < 8; j++) {
            int c = j * 8 + 2 * tig;
            float a0 = msk[c], a1 = msk[c + 1];
            sacc[j][0] = sacc[j][0] * 0.125f + a0;
            sacc[j][1] = sacc[j][1] * 0.125f + a1;
            sacc[j][2] = sacc[j][2] * 0.125f + a0;
            sacc[j][3] = sacc[j][3] * 0.125f + a1;
            tm0 = fmaxf(tm0, fmaxf(sacc[j][0], sacc[j][1]));
            tm1 = fmaxf(tm1, fmaxf(sacc[j][2], sacc[j][3]));
        }
        tm0 = fmaxf(tm0, __shfl_xor_sync(0xffffffffu, tm0, 1));
        tm0 = fmaxf(tm0, __shfl_xor_sync(0xffffffffu, tm0, 2));
        tm1 = fmaxf(tm1, __shfl_xor_sync(0xffffffffu, tm1, 1));
        tm1 = fmaxf(tm1, __shfl_xor_sync(0xffffffffu, tm1, 2));

        float mn0 = fmaxf(mr0, tm0), mn1 = fmaxf(mr1, tm1);
        float al0 = __expf(mr0 - mn0), al1 = __expf(mr1 - mn1);

        __syncwarp();
        float ts0 = 0.f, ts1 = 0.f;
        #pragma unroll
        for (int j = 0; j < 8; j++) {
            float p0v = __expf(sacc[j][0] - mn0);
            float p1v = __expf(sacc[j][1] - mn0);
            float p2v = __expf(sacc[j][2] - mn1);
            float p3v = __expf(sacc[j][3] - mn1);
            ts0 += p0v + p1v;
            ts1 += p2v + p3v;
            int m = j >> 1;
            int pi = (j & 1) * 4 + tig;
            int pos = 2 * (pi & 3) + (pi >> 2);
            *(__half2*)(Ps + (wr + g) * 40 + m * 8 + pos)     = __floats2half2_rn(p0v, p1v);
            *(__half2*)(Ps + (wr + g + 8) * 40 + m * 8 + pos) = __floats2half2_rn(p2v, p3v);
        }
        ts0 += __shfl_xor_sync(0xffffffffu, ts0, 1);
        ts0 += __shfl_xor_sync(0xffffffffu, ts0, 2);
        ts1 += __shfl_xor_sync(0xffffffffu, ts1, 1);
        ts1 += __shfl_xor_sync(0xffffffffu, ts1, 2);
        l0 = l0 * al0 + ts0;
        l1 = l1 * al1 + ts1;
        mr0 = mn0; mr1 = mn1;

        #pragma unroll
        for (int j = 0; j < 8; j++) {
            oacc[j][0] *= al0; oacc[j][1] *= al0;
            oacc[j][2] *= al1; oacc[j][3] *= al1;
        }
        __syncwarp();

        #pragma unroll
        for (int m = 0; m < 4; m++) {
            unsigned af[4];
            {
                uint2 pa = *(const uint2*)(Ps + (wr + g) * 40 + m * 8 + 2 * tig);
                uint2 pb = *(const uint2*)(Ps + (wr + g + 8) * 40 + m * 8 + 2 * tig);
                af[0] = pa.x; af[2] = pa.y;
                af[1] = pb.x; af[3] = pb.y;
            }
            #pragma unroll
            for (int j = 0; j < 8; j++) {
                uint2 pk = *(const uint2*)(Vs + m * 512 + (j * 8 + g) * 8 + 2 * tig);
                unsigned bf[2] = { pk.x, pk.y };
                mma_f16(oacc[j], af, bf);
            }
        }
    }

    // finalize; write ctx INTERLEAVED
    float il0 = 1.f / l0, il1 = 1.f / l1;
    int r0 = i0 + wr + g;
    #pragma unroll
    for (int j = 0; j < 8; j++) {
        int c = j * 8 + 2 * tig;
        int off = ilv_off(c);
        *(__half2*)&cb[(size_t)r0 * DD + off] =
            __floats2half2_rn(oacc[j][0] * il0, oacc[j][1] * il0);
        *(__half2*)&cb[(size_t)(r0 + 8) * DD + off] =
            __floats2half2_rn(oacc[j][2] * il1, oacc[j][3] * il1);
    }
}

// ---------------- LayerNorm(x (+ ra) (+ rb)); fp32 O + interleaved fp16 Or ----------------
// 192 threads x 4 elems (float4)
__global__ void k_addln3(const float* __restrict__ X, const float* __restrict__ RA,
                         const float* __restrict__ RB,
                         const float* __restrict__ g, const float* __restrict__ bb,
                         float* __restrict__ O, __half* __restrict__ Or)
{
    int r = blockIdx.x;
    const float* xrow = X + (size_t)r * DD;
    const float* ra = RA ? (RA + (size_t)r * DD) : nullptr;
    const float* rbp = RB ? (RB + (size_t)r * DD) : nullptr;
    float* orow = O + (size_t)r * DD;
    __half* orow2 = Or + (size_t)r * DD;

    int tid = threadIdx.x;
    int c0 = tid * 4;
    __shared__ float rbuf[6];

    float4 xv = *(const float4*)(xrow + c0);
    if (ra) {
        float4 t = *(const float4*)(ra + c0);
        xv.x += t.x; xv.y += t.y; xv.z += t.z; xv.w += t.w;
    }
    if (rbp) {
        float4 t = *(const float4*)(rbp + c0);
        xv.x += t.x; xv.y += t.y; xv.z += t.z; xv.w += t.w;
    }
    float s = xv.x + xv.y + xv.z + xv.w;
    #pragma unroll
    for (int o = 16; o; o >>= 1) s += __shfl_xor_sync(0xffffffffu, s, o);
    __syncthreads();
    if ((tid & 31) == 0) rbuf[tid >> 5] = s;
    __syncthreads();
    s = rbuf[0];
    #pragma unroll
    for (int w = 1; w < 6; w++) s += rbuf[w];
    float mean = s * (1.f / DD);

    float dx = xv.x - mean, dy = xv.y - mean, dz = xv.z - mean, dw = xv.w - mean;
    float s2 = dx * dx + dy * dy + dz * dz + dw * dw;
    #pragma unroll
    for (int o = 16; o; o >>= 1) s2 += __shfl_xor_sync(0xffffffffu, s2, o);
    __syncthreads();
    if ((tid & 31) == 0) rbuf[tid >> 5] = s2;
    __syncthreads();
    s2 = rbuf[0];
    #pragma unroll
    for (int w = 1; w < 6; w++) s2 += rbuf[w];
    float rstd = rsqrtf(s2 * (1.f / DD) + 1e-5f);

    float4 gv = *(const float4*)(g + c0);
    float4 bv = *(const float4*)(bb + c0);
    float u0 = dx * rstd * gv.x + bv.x;
    float u1 = dy * rstd * gv.y + bv.y;
    float u2 = dz * rstd * gv.z + bv.z;
    float u3 = dw * rstd * gv.w + bv.w;
    *(float4*)(orow + c0) = make_float4(u0, u1, u2, u3);
    *(__half2*)&orow2[ilv_off(c0)]     = __floats2half2_rn(u0, u1);
    *(__half2*)&orow2[ilv_off(c0 + 2)] = __floats2half2_rn(u2, u3);
}

// ---------------- driver ----------------
extern "C" void kernel_launch(void* const* d_in, const int* in_sizes, int n_in,
                              void* d_out, int out_size)
{
    const int*   ids  = (const int*)  d_in[0];
    const int*   mask = (const int*)  d_in[1];
    const float* emb  = (const float*)d_in[2];
    const float* pe   = (const float*)d_in[3];
    const float* Wq   = (const float*)d_in[4];
    const float* Wk   = (const float*)d_in[5];
    const float* Wv   = (const float*)d_in[6];
    const float* Wo   = (const float*)d_in[7];
    const float* ln1g = (const float*)d_in[8];
    const float* ln1b = (const float*)d_in[9];
    const float* ln2g = (const float*)d_in[10];
    const float* ln2b = (const float*)d_in[11];
    const float* W1   = (const float*)d_in[12];
    const float* b1   = (const float*)d_in[13];
    const float* W2   = (const float*)d_in[14];
    const float* b2   = (const float*)d_in[15];
    const float* lnfg = (const float*)d_in[16];
    const float* lnfb = (const float*)d_in[17];
    const float* Wout = (const float*)d_in[18];
    const float* bout = (const float*)d_in[19];
    float* out = (float*)d_out;

    float *x, *tmp, *tmp2;
    __half *xr, *qkv, *ctx, *h, *vti;
    __half *wqi, *wki, *wvi, *woi, *w1i, *w2i, *wpi;
    cudaGetSymbolAddress((void**)&x,    g_x);
    cudaGetSymbolAddress((void**)&xr,   g_xr);
    cudaGetSymbolAddress((void**)&qkv,  g_qkv);
    cudaGetSymbolAddress((void**)&ctx,  g_ctx);
    cudaGetSymbolAddress((void**)&tmp,  g_tmp);
    cudaGetSymbolAddress((void**)&tmp2, g_tmp2);
    cudaGetSymbolAddress((void**)&h,    g_h);
    cudaGetSymbolAddress((void**)&vti,  g_vti);
    cudaGetSymbolAddress((void**)&wqi,  g_wqi);
    cudaGetSymbolAddress((void**)&wki,  g_wki);
    cudaGetSymbolAddress((void**)&wvi,  g_wvi);
    cudaGetSymbolAddress((void**)&woi,  g_woi);
    cudaGetSymbolAddress((void**)&w1i,  g_w1i);
    cudaGetSymbolAddress((void**)&w2i,  g_w2i);
    cudaGetSymbolAddress((void**)&wpi,  g_wpi);

    __half* q = qkv;
    __half* k = qkv + (size_t)NT * DD;

    cudaFuncSetAttribute(k_fattn,   cudaFuncAttributeMaxDynamicSharedMemorySize, FA_SMEM);
    cudaFuncSetAttribute(k_gmma,    cudaFuncAttributeMaxDynamicSharedMemorySize, GM_SMEM);
    cudaFuncSetAttribute(k_gmma_m,  cudaFuncAttributeMaxDynamicSharedMemorySize, GM_SMEM);
    cudaFuncSetAttribute(k_gmma_sk, cudaFuncAttributeMaxDynamicSharedMemorySize, GM_SMEM);
    cudaFuncSetAttribute(k_qkv,     cudaFuncAttributeMaxDynamicSharedMemorySize, GM_SMEM);

    k_ilv<<<dim3(DD/64, DD/32, NL), 256>>>(Wq, wqi, DD, DD, DD);
    k_ilv<<<dim3(DD/64, DD/32, NL), 256>>>(Wk, wki, DD, DD, DD);
    k_ilv<<<dim3(DD/64, DD/32, NL), 256>>>(Wv, wvi, DD, DD, DD);
    k_ilv<<<dim3(DD/64, DD/32, NL), 256>>>(Wo, woi, DD, DD, DD);
    k_ilv<<<dim3(DD/64, FF/32, NL), 256>>>(W1, w1i, DD, FF, FF);
    k_ilv<<<dim3(FF/64, DD/32, NL), 256>>>(W2, w2i, FF, DD, DD);
    k_ilv<<<dim3(DD/64, NVP/32, 1), 256>>>(Wout, wpi, DD, NV, NVP);

    k_embed<<<(NT * DD / 2 + 255) / 256, 256>>>(ids, emb, pe, x, xr);

    dim3 gQKV(DD / 128, NT / 128, 3);
    dim3 gF(FF / 128, NT / 128);
    dim3 gSK(DD / 128, NT / 128, 2);
    dim3 gV(NT / 128, NVP / 128);
    dim3 gA(SQ / 128, BB * NH);

    for (int l = 0; l < NL; l++) {
        size_t od = (size_t)l * DD * DD;
        size_t of = (size_t)l * DD * FF;

        k_qkv<<<gQKV, 256, GM_SMEM>>>(xr, wqi + od, wki + od, wvi + od, qkv, vti);

        k_fattn<<<gA, 256, FA_SMEM>>>(q, k, vti, mask, ctx);

        k_gmma_sk<<<gSK, 256, GM_SMEM>>>(ctx, woi + od, nullptr, tmp, tmp2,
                                         DD, DD, DD, DD / 2);
        k_addln3<<<NT, 192>>>(x, tmp, tmp2, ln1g + (size_t)l * DD, ln1b + (size_t)l * DD, x, xr);

        k_gmma<<<gF, 256, GM_SMEM>>>(xr, w1i + of, b1 + (size_t)l * FF, nullptr, h,
                                     FF, FF, DD, 1, 1);

        k_gmma_sk<<<gSK, 256, GM_SMEM>>>(h, w2i + of, b2 + (size_t)l * DD, tmp, tmp2,
                                         DD, DD, FF, FF / 2);
        k_addln3<<<NT, 192>>>(x, tmp, tmp2, ln2g + (size_t)l * DD, ln2b + (size_t)l * DD, x, xr);
    }

    k_addln3<<<NT, 192>>>(x, nullptr, nullptr, lnfg, lnfb, x, xr);

    k_gmma_m<<<gV, 256, GM_SMEM>>>(xr, wpi, bout, out, NV, NVP, DD);
}